// round 16
// baseline (speedup 1.0000x reference)
#include <cuda_runtime.h>
#include <cuda_fp16.h>

#define NMAX 50000
#define EMAX 800000
#define CSR_GRID 592   // 4 blocks/SM x 148 SMs — co-resident by construction

// ---------------- f32x2 / half helpers (sm_103a) ----------------------------
#define DUP_F32X2(d, f) \
    asm("mov.b64 %0, {%1, %1};" : "=l"(d) : "f"(f))
#define UNPACK_F32X2(lo, hi, v) \
    asm("mov.b64 {%0, %1}, %2;" : "=f"(lo), "=f"(hi) : "l"(v))
#define FFMA2(d, a, b, c) \
    asm("fma.rn.f32x2 %0, %1, %2, %3;" : "=l"(d) : "l"(a), "l"(b), "l"(c))

__device__ __forceinline__ float4 f4add(float4 a, float4 b) {
    return make_float4(a.x + b.x, a.y + b.y, a.z + b.z, a.w + b.w);
}
__device__ __forceinline__ float4 f4fma(float s, float4 w, float4 a) {
    return make_float4(fmaf(s, w.x, a.x), fmaf(s, w.y, a.y),
                       fmaf(s, w.z, a.z), fmaf(s, w.w, a.w));
}
__device__ __forceinline__ float2 h2f(unsigned u) {
    __half2 h = *reinterpret_cast<__half2*>(&u);
    return __half22float2(h);
}
__device__ __forceinline__ unsigned f2h(float a, float b) {
    __half2 h = __floats2half2_rn(a, b);
    return *reinterpret_cast<unsigned*>(&h);
}

// accumulate 8 halves (one uint4) into 4 float2 accumulators S0..S3
#define ACC8(S0, S1, S2, S3, u) do { float2 _t;            \
    _t = h2f((u).x); S0.x += _t.x; S0.y += _t.y;           \
    _t = h2f((u).y); S1.x += _t.x; S1.y += _t.y;           \
    _t = h2f((u).z); S2.x += _t.x; S2.y += _t.y;           \
    _t = h2f((u).w); S3.x += _t.x; S3.y += _t.y; } while (0)

// ---------------- scratch (device globals; zero-init at load) ---------------
// protocol counters/flags are reset by the LAST kernel of every call, so each
// call starts from the zero state (deterministic; no caching of results).
__device__ __align__(16) int g_cnt[NMAX];      // re-zeroed in scan phase
__device__ __align__(16) int g_rowptr[NMAX + 4];
__device__ __align__(16) int g_cursor[NMAX];
__device__ int2   g_csr[EMAX];
__device__ int    g_blocksum[64];
__device__ volatile int g_flagv[64];  // scan lookback flags
__device__ int    g_done;             // hist-done counter
__device__ int    g_scandone;         // scan-done counter
__device__ uint2  g_p1h[NMAX * 16];   // x @ W1m_x  [N,64] fp16 (row = 128B)
__device__ float4 g_s1[NMAX * 16];    // x @ W1s    [N,64] fp32
__device__ uint2  g_p2h[NMAX * 8];    // h @ W2m_x  [N,32] fp16 (row = 64B)
__device__ float4 g_s2[NMAX * 8];     // h @ W2s    [N,32] fp32
__device__ float4 g_aggp[NMAX * 16];  // gathered projections, layer 1 (fp32)
__device__ float4 g_agge[NMAX * 4];   // segment_sum(edge_attr) [N,16] fp32

// ---------------- persistent CSR build: hist -> scan -> scatter -------------
__global__ __launch_bounds__(256, 4) void k_csr(
    const int* __restrict__ src, const int* __restrict__ dst,
    int E, int N, int SB)
{
    int tid = threadIdx.x, b = blockIdx.x;
    int G = gridDim.x;

    // --- phase 1: histogram (grid-stride) ---
    for (int e = b * 256 + tid; e < E; e += G * 256)
        atomicAdd(&g_cnt[dst[e]], 1);
    __threadfence();
    __syncthreads();
    if (tid == 0) atomicAdd(&g_done, 1);

    // --- phase 2: scan (blocks 0..SB-1; 1024 elems per block, 4/thread) ---
    __shared__ int sW[8];
    __shared__ int sOff;
    if (b < SB) {
        if (tid == 0) { while (*(volatile int*)&g_done < G) { } }
        __syncthreads();
        __threadfence();

        int base = b * 1024 + tid * 4;
        int4 c4 = make_int4(0, 0, 0, 0);
        if (base + 3 < N) {
            c4 = *(const int4*)&g_cnt[base];
        } else if (base < N) {
            c4.x = g_cnt[base];
            if (base + 1 < N) c4.y = g_cnt[base + 1];
            if (base + 2 < N) c4.z = g_cnt[base + 2];
        }
        int tot = c4.x + c4.y + c4.z + c4.w;
        int lane = tid & 31, wid = tid >> 5;
        int v = tot;
        #pragma unroll
        for (int o = 1; o < 32; o <<= 1) {
            int t = __shfl_up_sync(0xffffffffu, v, o);
            if (lane >= o) v += t;
        }
        if (lane == 31) sW[wid] = v;
        __syncthreads();
        if (tid < 8) {
            int w = sW[tid];
            #pragma unroll
            for (int o = 1; o < 8; o <<= 1) {
                int t = __shfl_up_sync(0xffu, w, o);
                if (tid >= o) w += t;
            }
            sW[tid] = w;
        }
        __syncthreads();
        if (tid == 0) {
            g_blocksum[b] = sW[7];
            __threadfence();
            g_flagv[b] = 1;
        }
        if (wid == 0) {
            int s = 0;
            for (int p = lane; p < b; p += 32) {
                while (g_flagv[p] != 1) { }
                s += g_blocksum[p];
            }
            #pragma unroll
            for (int o = 16; o > 0; o >>= 1)
                s += __shfl_down_sync(0xffffffffu, s, o);
            if (lane == 0) sOff = s;
        }
        __syncthreads();

        int excl = sOff + (wid ? sW[wid - 1] : 0) + (v - tot);
        int e0 = excl, e1 = e0 + c4.x, e2 = e1 + c4.y, e3 = e2 + c4.z;
        if (base + 3 < N) {
            *(int4*)&g_rowptr[base] = make_int4(e0, e1, e2, e3);
            *(int4*)&g_cursor[base] = make_int4(e0, e1, e2, e3);
            *(int4*)&g_cnt[base]    = make_int4(0, 0, 0, 0);
        } else if (base < N) {
            g_rowptr[base] = e0; g_cursor[base] = e0; g_cnt[base] = 0;
            if (base + 1 < N) { g_rowptr[base + 1] = e1; g_cursor[base + 1] = e1; g_cnt[base + 1] = 0; }
            if (base + 2 < N) { g_rowptr[base + 2] = e2; g_cursor[base + 2] = e2; g_cnt[base + 2] = 0; }
        }
        if (b == 0 && tid == 0) g_rowptr[N] = E;
        __threadfence();
        __syncthreads();
        if (tid == 0) atomicAdd(&g_scandone, 1);
    }

    // --- phase 3: scatter (all blocks, grid-stride) ---
    if (tid == 0) { while (*(volatile int*)&g_scandone < SB) { } }
    __syncthreads();
    __threadfence();
    for (int e = b * 256 + tid; e < E; e += G * 256) {
        int d = dst[e];
        int p = atomicAdd(&g_cursor[d], 1);
        g_csr[p] = make_int2(src[e], e);
    }
}

// ---------------- proj1: P1 = x@W1m[:64] (fp16), S1 = x@W1s (fp32) ----------
__global__ __launch_bounds__(256) void k_proj1(
    const float4* __restrict__ x4,
    const float4* __restrict__ W1m4,   // [80,64] -> f4 row stride 16
    const float4* __restrict__ W1s4,   // [64,64] -> f4 row stride 16
    int N)
{
    __shared__ __align__(16) float sXT[64 * 66];
    int tid = threadIdx.x;
    int nb = blockIdx.x * 64;
    int nn = N - nb; if (nn > 64) nn = 64;

    for (int idx = tid; idx < nn * 16; idx += 256) {
        int n = idx >> 4, c = idx & 15;
        float4 f = __ldg(&x4[(nb + n) * 16 + c]);
        sXT[(4 * c + 0) * 66 + n] = f.x;
        sXT[(4 * c + 1) * 66 + n] = f.y;
        sXT[(4 * c + 2) * 66 + n] = f.z;
        sXT[(4 * c + 3) * 66 + n] = f.w;
    }
    __syncthreads();

    int tx = tid & 31, ty = tid >> 5;    // 32 f4-cols, 8 node-groups
    int r0 = ty * 8;
    unsigned long long acc2[4][4];
    #pragma unroll
    for (int p = 0; p < 4; p++)
        #pragma unroll
        for (int c = 0; c < 4; c++) acc2[p][c] = 0ull;

    const float4* Wp = (tx < 16) ? (W1m4 + tx) : (W1s4 + (tx - 16));
    #pragma unroll 8
    for (int i = 0; i < 64; i++) {
        float4 w4 = __ldg(Wp + i * 16);
        unsigned long long wd0, wd1, wd2, wd3;
        DUP_F32X2(wd0, w4.x); DUP_F32X2(wd1, w4.y);
        DUP_F32X2(wd2, w4.z); DUP_F32X2(wd3, w4.w);
        #pragma unroll
        for (int p = 0; p < 4; p++) {
            unsigned long long v2 =
                *(const unsigned long long*)&sXT[i * 66 + r0 + 2 * p];
            FFMA2(acc2[p][0], v2, wd0, acc2[p][0]);
            FFMA2(acc2[p][1], v2, wd1, acc2[p][1]);
            FFMA2(acc2[p][2], v2, wd2, acc2[p][2]);
            FFMA2(acc2[p][3], v2, wd3, acc2[p][3]);
        }
    }

    bool isP = (tx < 16);
    int txo = isP ? tx : tx - 16;
    #pragma unroll
    for (int p = 0; p < 4; p++) {
        float lo[4], hi[4];
        #pragma unroll
        for (int c = 0; c < 4; c++) UNPACK_F32X2(lo[c], hi[c], acc2[p][c]);
        int r = r0 + 2 * p;
        if (isP) {
            if (r < nn)
                g_p1h[(nb + r) * 16 + txo] =
                    make_uint2(f2h(lo[0], lo[1]), f2h(lo[2], lo[3]));
            if (r + 1 < nn)
                g_p1h[(nb + r + 1) * 16 + txo] =
                    make_uint2(f2h(hi[0], hi[1]), f2h(hi[2], hi[3]));
        } else {
            if (r < nn)
                g_s1[(nb + r) * 16 + txo] = make_float4(lo[0], lo[1], lo[2], lo[3]);
            if (r + 1 < nn)
                g_s1[(nb + r + 1) * 16 + txo] = make_float4(hi[0], hi[1], hi[2], hi[3]);
        }
    }
}

// ---------------- gather1: quarter-warp per node, fp16 payload, slim regs ----
__global__ __launch_bounds__(256) void k_gather1(const float4* __restrict__ ea4, int N) {
    int warp = (blockIdx.x * 256 + threadIdx.x) >> 5;
    int lane = threadIdx.x & 31;
    int g = lane >> 3, j = lane & 7;
    int node = warp * 4 + g;
    if (node >= N) return;
    int beg = g_rowptr[node];
    int cnt = g_rowptr[node + 1] - beg;
    const int2* csr = g_csr + beg;
    const uint4* p1 = (const uint4*)g_p1h;   // row stride 8 uint4

    float2 A0 = {0,0}, A1 = {0,0}, A2 = {0,0}, A3 = {0,0};
    float4 e0 = {0,0,0,0};

    int k = 0;
    for (; k + 4 <= cnt; k += 4) {
        int2 c0 = csr[k], c1 = csr[k + 1], c2 = csr[k + 2], c3 = csr[k + 3];
        uint4 u0 = __ldg(&p1[c0.x * 8 + j]);
        uint4 u1 = __ldg(&p1[c1.x * 8 + j]);
        uint4 u2 = __ldg(&p1[c2.x * 8 + j]);
        uint4 u3 = __ldg(&p1[c3.x * 8 + j]);
        if (j < 4) {
            e0 = f4add(e0, f4add(
                f4add(__ldg(&ea4[c0.y * 4 + j]), __ldg(&ea4[c1.y * 4 + j])),
                f4add(__ldg(&ea4[c2.y * 4 + j]), __ldg(&ea4[c3.y * 4 + j]))));
        }
        ACC8(A0, A1, A2, A3, u0);
        ACC8(A0, A1, A2, A3, u1);
        ACC8(A0, A1, A2, A3, u2);
        ACC8(A0, A1, A2, A3, u3);
    }
    for (; k < cnt; k++) {
        int2 c0 = csr[k];
        uint4 u0 = __ldg(&p1[c0.x * 8 + j]);
        if (j < 4) e0 = f4add(e0, __ldg(&ea4[c0.y * 4 + j]));
        ACC8(A0, A1, A2, A3, u0);
    }
    g_aggp[node * 16 + 2 * j]     = make_float4(A0.x, A0.y, A1.x, A1.y);
    g_aggp[node * 16 + 2 * j + 1] = make_float4(A2.x, A2.y, A3.x, A3.y);
    if (j < 4) g_agge[node * 4 + j] = e0;
}

// ---------------- node1 + proj2 (P2 stored fp16) ------------------------------
__global__ __launch_bounds__(256) void k_node1p2(
    const float* __restrict__ W1m,     // [80,64] scalar (edge rows 64..79)
    const float* __restrict__ b1s, const float* __restrict__ b1m,
    const float* __restrict__ gamma, const float* __restrict__ beta,
    const float* __restrict__ mean, const float* __restrict__ var,
    const float4* __restrict__ W2m4,   // [80,32] -> f4 row stride 8
    const float4* __restrict__ W2s4,   // [64,32] -> f4 row stride 8
    int N)
{
    __shared__ __align__(16) float sHT[64 * 66];
    int tid = threadIdx.x;
    int nb = blockIdx.x * 64;
    int nn = N - nb; if (nn > 64) nn = 64;

    // --- phase A: compute h (thread = node x 16-col group) ---
    {
        int n = tid >> 2;
        int cg = (tid & 3) * 4;
        if (n < nn) {
            int node = nb + n;
            float deg = (float)(g_rowptr[node + 1] - g_rowptr[node]);
            float4 eg4[4];
            #pragma unroll
            for (int q = 0; q < 4; q++) eg4[q] = g_agge[node * 4 + q];
            float eg[16] = {eg4[0].x, eg4[0].y, eg4[0].z, eg4[0].w,
                            eg4[1].x, eg4[1].y, eg4[1].z, eg4[1].w,
                            eg4[2].x, eg4[2].y, eg4[2].z, eg4[2].w,
                            eg4[3].x, eg4[3].y, eg4[3].z, eg4[3].w};
            float4 acc[4];
            #pragma unroll
            for (int q = 0; q < 4; q++) {
                float4 s  = g_s1[node * 16 + cg + q];
                float4 a  = g_aggp[node * 16 + cg + q];
                float4 bS = __ldg(&((const float4*)b1s)[cg + q]);
                float4 bM = __ldg(&((const float4*)b1m)[cg + q]);
                acc[q] = make_float4(s.x + a.x + bS.x + deg * bM.x,
                                     s.y + a.y + bS.y + deg * bM.y,
                                     s.z + a.z + bS.z + deg * bM.z,
                                     s.w + a.w + bS.w + deg * bM.w);
            }
            #pragma unroll
            for (int jj = 0; jj < 16; jj++) {
                float ev = eg[jj];
                const float4* wrow = (const float4*)(W1m + (64 + jj) * 64) + cg;
                #pragma unroll
                for (int q = 0; q < 4; q++)
                    acc[q] = f4fma(ev, __ldg(&wrow[q]), acc[q]);
            }
            #pragma unroll
            for (int q = 0; q < 4; q++) {
                float4 gm = __ldg(&((const float4*)gamma)[cg + q]);
                float4 vv = __ldg(&((const float4*)var)[cg + q]);
                float4 mn = __ldg(&((const float4*)mean)[cg + q]);
                float4 bt = __ldg(&((const float4*)beta)[cg + q]);
                float scx = gm.x * rsqrtf(vv.x + 1e-5f);
                float scy = gm.y * rsqrtf(vv.y + 1e-5f);
                float scz = gm.z * rsqrtf(vv.z + 1e-5f);
                float scw = gm.w * rsqrtf(vv.w + 1e-5f);
                float hx = fmaxf(acc[q].x * scx + (bt.x - mn.x * scx), 0.f);
                float hy = fmaxf(acc[q].y * scy + (bt.y - mn.y * scy), 0.f);
                float hz = fmaxf(acc[q].z * scz + (bt.z - mn.z * scz), 0.f);
                float hw = fmaxf(acc[q].w * scw + (bt.w - mn.w * scw), 0.f);
                int c0 = (cg + q) * 4;
                sHT[(c0 + 0) * 66 + n] = hx;
                sHT[(c0 + 1) * 66 + n] = hy;
                sHT[(c0 + 2) * 66 + n] = hz;
                sHT[(c0 + 3) * 66 + n] = hw;
            }
        }
    }
    __syncthreads();

    // --- phase B: GEMM h[64,64] @ [W2m_x | W2s] -> P2 (fp16), S2 (fp32) ---
    int tx = tid & 15, ty = tid >> 4;
    int r0 = ty * 4;
    unsigned long long acc2[2][4];
    #pragma unroll
    for (int p = 0; p < 2; p++)
        #pragma unroll
        for (int c = 0; c < 4; c++) acc2[p][c] = 0ull;

    const float4* Wp = (tx < 8) ? (W2m4 + tx) : (W2s4 + (tx - 8));
    #pragma unroll 8
    for (int i = 0; i < 64; i++) {
        float4 w4 = __ldg(Wp + i * 8);
        unsigned long long wd0, wd1, wd2, wd3;
        DUP_F32X2(wd0, w4.x); DUP_F32X2(wd1, w4.y);
        DUP_F32X2(wd2, w4.z); DUP_F32X2(wd3, w4.w);
        #pragma unroll
        for (int p = 0; p < 2; p++) {
            unsigned long long v2 =
                *(const unsigned long long*)&sHT[i * 66 + r0 + 2 * p];
            FFMA2(acc2[p][0], v2, wd0, acc2[p][0]);
            FFMA2(acc2[p][1], v2, wd1, acc2[p][1]);
            FFMA2(acc2[p][2], v2, wd2, acc2[p][2]);
            FFMA2(acc2[p][3], v2, wd3, acc2[p][3]);
        }
    }

    bool isP = (tx < 8);
    int txo = isP ? tx : tx - 8;
    #pragma unroll
    for (int p = 0; p < 2; p++) {
        float lo[4], hi[4];
        #pragma unroll
        for (int c = 0; c < 4; c++) UNPACK_F32X2(lo[c], hi[c], acc2[p][c]);
        int r = r0 + 2 * p;
        if (isP) {
            if (r < nn)
                g_p2h[(nb + r) * 8 + txo] =
                    make_uint2(f2h(lo[0], lo[1]), f2h(lo[2], lo[3]));
            if (r + 1 < nn)
                g_p2h[(nb + r + 1) * 8 + txo] =
                    make_uint2(f2h(hi[0], hi[1]), f2h(hi[2], hi[3]));
        } else {
            if (r < nn)
                g_s2[(nb + r) * 8 + txo] = make_float4(lo[0], lo[1], lo[2], lo[3]);
            if (r + 1 < nn)
                g_s2[(nb + r + 1) * 8 + txo] = make_float4(hi[0], hi[1], hi[2], hi[3]);
        }
    }
}

// ---------------- fused gather2 + node2 (fp16 payload, slim regs) ------------
__global__ __launch_bounds__(256) void k_gather2node2(
    const float4* __restrict__ W2m4,   // [80,32] -> f4 row stride 8
    const float* __restrict__ b2s, const float* __restrict__ b2m,
    float4* __restrict__ out4, int N)
{
    // reset persistent-kernel protocol state for the NEXT call (this kernel is
    // last in the per-call sequence; stream order guarantees visibility).
    if (blockIdx.x == 0) {
        if (threadIdx.x < 64) g_flagv[threadIdx.x] = 0;
        if (threadIdx.x == 0) { g_done = 0; g_scandone = 0; }
    }

    int t = blockIdx.x * 256 + threadIdx.x;
    int node = t >> 3;
    int j = t & 7;
    if (node >= N) return;
    int beg = g_rowptr[node];
    int cnt = g_rowptr[node + 1] - beg;
    const int2* csr = g_csr + beg;
    const uint2* p2 = (const uint2*)g_p2h;   // row stride 8 uint2

    float2 A0 = {0,0}, A1 = {0,0};
    int k = 0;
    for (; k + 4 <= cnt; k += 4) {
        int2 c0 = csr[k], c1 = csr[k + 1], c2 = csr[k + 2], c3 = csr[k + 3];
        uint2 u0 = __ldg(&p2[c0.x * 8 + j]);
        uint2 u1 = __ldg(&p2[c1.x * 8 + j]);
        uint2 u2 = __ldg(&p2[c2.x * 8 + j]);
        uint2 u3 = __ldg(&p2[c3.x * 8 + j]);
        float2 s;
        s = h2f(u0.x); A0.x += s.x; A0.y += s.y;
        s = h2f(u0.y); A1.x += s.x; A1.y += s.y;
        s = h2f(u1.x); A0.x += s.x; A0.y += s.y;
        s = h2f(u1.y); A1.x += s.x; A1.y += s.y;
        s = h2f(u2.x); A0.x += s.x; A0.y += s.y;
        s = h2f(u2.y); A1.x += s.x; A1.y += s.y;
        s = h2f(u3.x); A0.x += s.x; A0.y += s.y;
        s = h2f(u3.y); A1.x += s.x; A1.y += s.y;
    }
    for (; k < cnt; k++) {
        int2 c0 = csr[k];
        uint2 u0 = __ldg(&p2[c0.x * 8 + j]);
        float2 s;
        s = h2f(u0.x); A0.x += s.x; A0.y += s.y;
        s = h2f(u0.y); A1.x += s.x; A1.y += s.y;
    }
    float4 o = make_float4(A0.x, A0.y, A1.x, A1.y);

    // epilogue: + S2 + b2s + deg*b2m + agge @ W2m_edge
    float deg = (float)cnt;
    float4 s2 = g_s2[node * 8 + j];
    float4 bS = __ldg(&((const float4*)b2s)[j]);
    float4 bM = __ldg(&((const float4*)b2m)[j]);
    o = make_float4(o.x + s2.x + bS.x + deg * bM.x,
                    o.y + s2.y + bS.y + deg * bM.y,
                    o.z + s2.z + bS.z + deg * bM.z,
                    o.w + s2.w + bS.w + deg * bM.w);
    float4 eg4[4];
    #pragma unroll
    for (int q = 0; q < 4; q++) eg4[q] = g_agge[node * 4 + q];
    float eg[16] = {eg4[0].x, eg4[0].y, eg4[0].z, eg4[0].w,
                    eg4[1].x, eg4[1].y, eg4[1].z, eg4[1].w,
                    eg4[2].x, eg4[2].y, eg4[2].z, eg4[2].w,
                    eg4[3].x, eg4[3].y, eg4[3].z, eg4[3].w};
    #pragma unroll
    for (int jj = 0; jj < 16; jj++)
        o = f4fma(eg[jj], __ldg(&W2m4[(64 + jj) * 8 + j]), o);

    out4[node * 8 + j] = o;
}

// ---------------- host --------------------------------------------------------
extern "C" void kernel_launch(void* const* d_in, const int* in_sizes, int n_in,
                              void* d_out, int out_size) {
    const float* x    = (const float*)d_in[0];
    const int*   ei   = (const int*)d_in[1];      // int32 (JAX x64 disabled)
    const float* ea   = (const float*)d_in[2];
    const float* W1m  = (const float*)d_in[3];
    const float* b1m  = (const float*)d_in[4];
    const float* W1s  = (const float*)d_in[5];
    const float* b1s  = (const float*)d_in[6];
    const float* gma  = (const float*)d_in[7];
    const float* bta  = (const float*)d_in[8];
    const float* mu   = (const float*)d_in[9];
    const float* var  = (const float*)d_in[10];
    const float* W2m  = (const float*)d_in[11];
    const float* b2m  = (const float*)d_in[12];
    const float* W2s  = (const float*)d_in[13];
    const float* b2s  = (const float*)d_in[14];

    int N = in_sizes[0] / 64;
    int E = in_sizes[1] / 2;
    const int* src = ei;
    const int* dst = ei + E;
    int SB = (N + 1023) / 1024;
    int PB = (N + 63) / 64;

    // one-time host-side objects (no device work, no device allocation)
    static cudaStream_t s2 = nullptr;
    static cudaEvent_t evFork = nullptr, evJoin = nullptr;
    if (s2 == nullptr) {
        cudaStreamCreateWithFlags(&s2, cudaStreamNonBlocking);
        cudaEventCreateWithFlags(&evFork, cudaEventDisableTiming);
        cudaEventCreateWithFlags(&evJoin, cudaEventDisableTiming);
    }

    // fork point BEFORE the CSR kernel so proj1 doesn't depend on it
    cudaEventRecord(evFork, 0);

    // persistent CSR build on main stream (launched first -> wave-1 priority)
    k_csr<<<CSR_GRID, 256>>>(src, dst, E, N, SB);

    // proj1 on the forked stream, concurrent with CSR build
    cudaStreamWaitEvent(s2, evFork, 0);
    k_proj1<<<PB, 256, 0, s2>>>((const float4*)x, (const float4*)W1m,
                                (const float4*)W1s, N);
    cudaEventRecord(evJoin, s2);

    // join: gather1 needs proj1 + CSR
    cudaStreamWaitEvent(0, evJoin, 0);
    k_gather1<<<(N * 8 + 255) / 256, 256>>>((const float4*)ea, N);
    k_node1p2<<<PB, 256>>>(W1m, b1s, b1m, gma, bta, mu, var,
                           (const float4*)W2m, (const float4*)W2s, N);
    k_gather2node2<<<(N * 8 + 255) / 256, 256>>>((const float4*)W2m, b2s, b2m,
                                                 (float4*)d_out, N);
}

// round 17
// speedup vs baseline: 1.1161x; 1.1161x over previous
#include <cuda_runtime.h>
#include <cuda_fp16.h>

#define NMAX 50000
#define EMAX 800000

// ---------------- f32x2 / half helpers (sm_103a) ----------------------------
#define DUP_F32X2(d, f) \
    asm("mov.b64 %0, {%1, %1};" : "=l"(d) : "f"(f))
#define UNPACK_F32X2(lo, hi, v) \
    asm("mov.b64 {%0, %1}, %2;" : "=f"(lo), "=f"(hi) : "l"(v))
#define FFMA2(d, a, b, c) \
    asm("fma.rn.f32x2 %0, %1, %2, %3;" : "=l"(d) : "l"(a), "l"(b), "l"(c))

__device__ __forceinline__ float4 f4add(float4 a, float4 b) {
    return make_float4(a.x + b.x, a.y + b.y, a.z + b.z, a.w + b.w);
}
__device__ __forceinline__ float4 f4fma(float s, float4 w, float4 a) {
    return make_float4(fmaf(s, w.x, a.x), fmaf(s, w.y, a.y),
                       fmaf(s, w.z, a.z), fmaf(s, w.w, a.w));
}
__device__ __forceinline__ float2 h2f(unsigned u) {
    __half2 h = *reinterpret_cast<__half2*>(&u);
    return __half22float2(h);
}
__device__ __forceinline__ unsigned f2h(float a, float b) {
    __half2 h = __floats2half2_rn(a, b);
    return *reinterpret_cast<unsigned*>(&h);
}

// accumulate 8 halves (one uint4) into 4 float2 accumulators S0..S3
#define ACC8(S0, S1, S2, S3, u) do { float2 _t;            \
    _t = h2f((u).x); S0.x += _t.x; S0.y += _t.y;           \
    _t = h2f((u).y); S1.x += _t.x; S1.y += _t.y;           \
    _t = h2f((u).z); S2.x += _t.x; S2.y += _t.y;           \
    _t = h2f((u).w); S3.x += _t.x; S3.y += _t.y; } while (0)

// ---------------- scratch (device globals; zero-init at load) ---------------
__device__ int    g_cnt[NMAX];        // self-restoring: re-zeroed in k_scan
__device__ int    g_rowptr[NMAX + 1];
__device__ int    g_cursor[NMAX];
__device__ int2   g_csr[EMAX];
__device__ int    g_blocksum[64];
__device__ volatile int g_flag[64];   // lookback flags (epoch-stamped)
__device__ int    g_epoch;            // bumped once per call
__device__ uint2  g_p1h[NMAX * 16];   // x @ W1m_x  [N,64] fp16 (row = 128B)
__device__ float4 g_s1[NMAX * 16];    // x @ W1s    [N,64] fp32
__device__ uint2  g_p2h[NMAX * 8];    // h @ W2m_x  [N,32] fp16 (row = 64B)
__device__ float4 g_s2[NMAX * 8];     // h @ W2s    [N,32] fp32
__device__ float4 g_aggp[NMAX * 16];  // gathered projections, layer 1 (fp32)
__device__ float4 g_agge[NMAX * 4];   // segment_sum(edge_attr) [N,16] fp32

// ---------------- CSR build (R15-proven) -------------------------------------
__global__ void k_hist(const int* __restrict__ dst, int E) {
    if (blockIdx.x == 0 && threadIdx.x == 0) g_epoch += 1;   // new scan epoch
    int e = blockIdx.x * blockDim.x + threadIdx.x;
    if (e < E) atomicAdd(&g_cnt[dst[e]], 1);
}

__global__ void k_scan(int N, int E) {
    int b = blockIdx.x;
    int i = b * 1024 + threadIdx.x;
    int lane = threadIdx.x & 31, wid = threadIdx.x >> 5;
    __shared__ int sW[32];
    __shared__ int sOff;
    int epoch = g_epoch;

    int c = (i < N) ? g_cnt[i] : 0;
    int v = c;
    #pragma unroll
    for (int o = 1; o < 32; o <<= 1) {
        int t = __shfl_up_sync(0xffffffffu, v, o);
        if (lane >= o) v += t;
    }
    if (lane == 31) sW[wid] = v;
    __syncthreads();
    if (wid == 0) {
        int w = sW[lane];
        #pragma unroll
        for (int o = 1; o < 32; o <<= 1) {
            int t = __shfl_up_sync(0xffffffffu, w, o);
            if (lane >= o) w += t;
        }
        sW[lane] = w;
    }
    __syncthreads();
    int total = sW[31];

    if (threadIdx.x == 0) {
        g_blocksum[b] = total;
        __threadfence();
        g_flag[b] = epoch;
    }
    if (wid == 0) {
        int s = 0;
        for (int p = lane; p < b; p += 32) {
            while (g_flag[p] != epoch) { }
            s += g_blocksum[p];
        }
        #pragma unroll
        for (int o = 16; o > 0; o >>= 1) s += __shfl_down_sync(0xffffffffu, s, o);
        if (lane == 0) sOff = s;
    }
    __syncthreads();

    if (i < N) {
        int excl = sOff + (wid ? sW[wid - 1] : 0) + v - c;
        g_rowptr[i] = excl;
        g_cursor[i] = excl;
        g_cnt[i] = 0;            // restore zero-init invariant for next call
    }
    if (b == 0 && threadIdx.x == 0) g_rowptr[N] = E;
}

__global__ void k_scatter(const int* __restrict__ src,
                          const int* __restrict__ dst, int E) {
    int e = blockIdx.x * blockDim.x + threadIdx.x;
    if (e < E) {
        int d = dst[e];
        int p = atomicAdd(&g_cursor[d], 1);
        g_csr[p] = make_int2(src[e], e);
    }
}

// ---------------- proj1: P1 = x@W1m[:64] (fp16), S1 = x@W1s (fp32) ----------
__global__ __launch_bounds__(256) void k_proj1(
    const float4* __restrict__ x4,
    const float4* __restrict__ W1m4,   // [80,64] -> f4 row stride 16
    const float4* __restrict__ W1s4,   // [64,64] -> f4 row stride 16
    int N)
{
    __shared__ __align__(16) float sXT[64 * 66];
    int tid = threadIdx.x;
    int nb = blockIdx.x * 64;
    int nn = N - nb; if (nn > 64) nn = 64;

    for (int idx = tid; idx < nn * 16; idx += 256) {
        int n = idx >> 4, c = idx & 15;
        float4 f = __ldg(&x4[(nb + n) * 16 + c]);
        sXT[(4 * c + 0) * 66 + n] = f.x;
        sXT[(4 * c + 1) * 66 + n] = f.y;
        sXT[(4 * c + 2) * 66 + n] = f.z;
        sXT[(4 * c + 3) * 66 + n] = f.w;
    }
    __syncthreads();

    int tx = tid & 31, ty = tid >> 5;    // 32 f4-cols, 8 node-groups
    int r0 = ty * 8;
    unsigned long long acc2[4][4];
    #pragma unroll
    for (int p = 0; p < 4; p++)
        #pragma unroll
        for (int c = 0; c < 4; c++) acc2[p][c] = 0ull;

    const float4* Wp = (tx < 16) ? (W1m4 + tx) : (W1s4 + (tx - 16));
    #pragma unroll 8
    for (int i = 0; i < 64; i++) {
        float4 w4 = __ldg(Wp + i * 16);
        unsigned long long wd0, wd1, wd2, wd3;
        DUP_F32X2(wd0, w4.x); DUP_F32X2(wd1, w4.y);
        DUP_F32X2(wd2, w4.z); DUP_F32X2(wd3, w4.w);
        #pragma unroll
        for (int p = 0; p < 4; p++) {
            unsigned long long v2 =
                *(const unsigned long long*)&sXT[i * 66 + r0 + 2 * p];
            FFMA2(acc2[p][0], v2, wd0, acc2[p][0]);
            FFMA2(acc2[p][1], v2, wd1, acc2[p][1]);
            FFMA2(acc2[p][2], v2, wd2, acc2[p][2]);
            FFMA2(acc2[p][3], v2, wd3, acc2[p][3]);
        }
    }

    bool isP = (tx < 16);
    int txo = isP ? tx : tx - 16;
    #pragma unroll
    for (int p = 0; p < 4; p++) {
        float lo[4], hi[4];
        #pragma unroll
        for (int c = 0; c < 4; c++) UNPACK_F32X2(lo[c], hi[c], acc2[p][c]);
        int r = r0 + 2 * p;
        if (isP) {
            if (r < nn)
                g_p1h[(nb + r) * 16 + txo] =
                    make_uint2(f2h(lo[0], lo[1]), f2h(lo[2], lo[3]));
            if (r + 1 < nn)
                g_p1h[(nb + r + 1) * 16 + txo] =
                    make_uint2(f2h(hi[0], hi[1]), f2h(hi[2], hi[3]));
        } else {
            if (r < nn)
                g_s1[(nb + r) * 16 + txo] = make_float4(lo[0], lo[1], lo[2], lo[3]);
            if (r + 1 < nn)
                g_s1[(nb + r + 1) * 16 + txo] = make_float4(hi[0], hi[1], hi[2], hi[3]);
        }
    }
}

// ---------------- gather1 (R15-proven): quarter-warp per node, 4-unroll ------
__global__ __launch_bounds__(256) void k_gather1(const float4* __restrict__ ea4, int N) {
    int warp = (blockIdx.x * 256 + threadIdx.x) >> 5;
    int lane = threadIdx.x & 31;
    int g = lane >> 3, j = lane & 7;
    int node = warp * 4 + g;
    if (node >= N) return;
    int beg = g_rowptr[node];
    int cnt = g_rowptr[node + 1] - beg;
    const int2* csr = g_csr + beg;
    const uint4* p1 = (const uint4*)g_p1h;   // row stride 8 uint4

    float2 A0 = {0,0}, A1 = {0,0}, A2 = {0,0}, A3 = {0,0};
    float2 B0 = {0,0}, B1 = {0,0}, B2 = {0,0}, B3 = {0,0};
    float4 e0 = {0,0,0,0}, e1 = e0;

    int k = 0;
    for (; k + 4 <= cnt; k += 4) {
        int2 c0 = csr[k], c1 = csr[k + 1], c2 = csr[k + 2], c3 = csr[k + 3];
        uint4 u0 = __ldg(&p1[c0.x * 8 + j]);
        uint4 u1 = __ldg(&p1[c1.x * 8 + j]);
        uint4 u2 = __ldg(&p1[c2.x * 8 + j]);
        uint4 u3 = __ldg(&p1[c3.x * 8 + j]);
        if (j < 4) {
            e0 = f4add(e0, f4add(__ldg(&ea4[c0.y * 4 + j]), __ldg(&ea4[c1.y * 4 + j])));
            e1 = f4add(e1, f4add(__ldg(&ea4[c2.y * 4 + j]), __ldg(&ea4[c3.y * 4 + j])));
        }
        ACC8(A0, A1, A2, A3, u0);
        ACC8(B0, B1, B2, B3, u1);
        ACC8(A0, A1, A2, A3, u2);
        ACC8(B0, B1, B2, B3, u3);
    }
    for (; k < cnt; k++) {
        int2 c0 = csr[k];
        uint4 u0 = __ldg(&p1[c0.x * 8 + j]);
        if (j < 4) e0 = f4add(e0, __ldg(&ea4[c0.y * 4 + j]));
        ACC8(A0, A1, A2, A3, u0);
    }
    g_aggp[node * 16 + 2 * j] =
        make_float4(A0.x + B0.x, A0.y + B0.y, A1.x + B1.x, A1.y + B1.y);
    g_aggp[node * 16 + 2 * j + 1] =
        make_float4(A2.x + B2.x, A2.y + B2.y, A3.x + B3.x, A3.y + B3.y);
    if (j < 4) g_agge[node * 4 + j] = f4add(e0, e1);
}

// ---------------- node1 + proj2 (restructured: GEMM for agge@W1m_e) ----------
__global__ __launch_bounds__(256) void k_node1p2(
    const float* __restrict__ W1m,     // [80,64] scalar (edge rows 64..79)
    const float* __restrict__ b1s, const float* __restrict__ b1m,
    const float* __restrict__ gamma, const float* __restrict__ beta,
    const float* __restrict__ mean, const float* __restrict__ var,
    const float4* __restrict__ W2m4,   // [80,32] -> f4 row stride 8
    const float4* __restrict__ W2s4,   // [64,32] -> f4 row stride 8
    int N)
{
    __shared__ __align__(16) float sAT[16 * 66];   // agge transposed
    __shared__ __align__(16) float sHT[64 * 66];   // h transposed
    int tid = threadIdx.x;
    int nb = blockIdx.x * 64;
    int nn = N - nb; if (nn > 64) nn = 64;

    // stage agge transposed: sAT[k][node]
    for (int idx = tid; idx < nn * 4; idx += 256) {
        int n = idx >> 2, q = idx & 3;
        float4 f = g_agge[(nb + n) * 4 + q];
        sAT[(4 * q + 0) * 66 + n] = f.x;
        sAT[(4 * q + 1) * 66 + n] = f.y;
        sAT[(4 * q + 2) * 66 + n] = f.z;
        sAT[(4 * q + 3) * 66 + n] = f.w;
    }
    __syncthreads();

    int tx = tid & 15, ty = tid >> 4;   // 16 f4-cols, 16 node-groups of 4
    int r0 = ty * 4;

    // --- GEMM1: acc = agge[64,16] @ W1m_edge[16,64] (FFMA2) ---
    unsigned long long accA[2][4];
    #pragma unroll
    for (int p = 0; p < 2; p++)
        #pragma unroll
        for (int c = 0; c < 4; c++) accA[p][c] = 0ull;

    const float4* WeP = (const float4*)(W1m + 64 * 64) + tx;   // edge rows
    #pragma unroll
    for (int i = 0; i < 16; i++) {
        float4 w4 = __ldg(WeP + i * 16);
        unsigned long long wd0, wd1, wd2, wd3;
        DUP_F32X2(wd0, w4.x); DUP_F32X2(wd1, w4.y);
        DUP_F32X2(wd2, w4.z); DUP_F32X2(wd3, w4.w);
        #pragma unroll
        for (int p = 0; p < 2; p++) {
            unsigned long long v2 =
                *(const unsigned long long*)&sAT[i * 66 + r0 + 2 * p];
            FFMA2(accA[p][0], v2, wd0, accA[p][0]);
            FFMA2(accA[p][1], v2, wd1, accA[p][1]);
            FFMA2(accA[p][2], v2, wd2, accA[p][2]);
            FFMA2(accA[p][3], v2, wd3, accA[p][3]);
        }
    }

    // --- epilogue per (node, 4-col slice): h = ReLU(BN(acc+S1+aggp+b1s+deg*b1m))
    {
        float4 bS = __ldg((const float4*)b1s + tx);
        float4 bM = __ldg((const float4*)b1m + tx);
        float4 gm = __ldg((const float4*)gamma + tx);
        float4 vv = __ldg((const float4*)var + tx);
        float4 mn = __ldg((const float4*)mean + tx);
        float4 bt = __ldg((const float4*)beta + tx);
        float scx = gm.x * rsqrtf(vv.x + 1e-5f), shx = bt.x - mn.x * scx;
        float scy = gm.y * rsqrtf(vv.y + 1e-5f), shy = bt.y - mn.y * scy;
        float scz = gm.z * rsqrtf(vv.z + 1e-5f), shz = bt.z - mn.z * scz;
        float scw = gm.w * rsqrtf(vv.w + 1e-5f), shw = bt.w - mn.w * scw;

        #pragma unroll
        for (int p = 0; p < 2; p++) {
            float lo[4], hi[4];
            #pragma unroll
            for (int c = 0; c < 4; c++) UNPACK_F32X2(lo[c], hi[c], accA[p][c]);
            #pragma unroll
            for (int h = 0; h < 2; h++) {
                int r = r0 + 2 * p + h;
                if (r < nn) {
                    int node = nb + r;
                    float deg = (float)(g_rowptr[node + 1] - g_rowptr[node]);
                    float4 s  = g_s1[node * 16 + tx];
                    float4 a  = g_aggp[node * 16 + tx];
                    float vx = (h ? hi[0] : lo[0]) + s.x + a.x + bS.x + deg * bM.x;
                    float vy = (h ? hi[1] : lo[1]) + s.y + a.y + bS.y + deg * bM.y;
                    float vz = (h ? hi[2] : lo[2]) + s.z + a.z + bS.z + deg * bM.z;
                    float vw = (h ? hi[3] : lo[3]) + s.w + a.w + bS.w + deg * bM.w;
                    int c0 = tx * 4;
                    sHT[(c0 + 0) * 66 + r] = fmaxf(vx * scx + shx, 0.f);
                    sHT[(c0 + 1) * 66 + r] = fmaxf(vy * scy + shy, 0.f);
                    sHT[(c0 + 2) * 66 + r] = fmaxf(vz * scz + shz, 0.f);
                    sHT[(c0 + 3) * 66 + r] = fmaxf(vw * scw + shw, 0.f);
                }
            }
        }
    }
    __syncthreads();

    // --- phase B: GEMM h[64,64] @ [W2m_x | W2s] -> P2 (fp16), S2 (fp32) ---
    unsigned long long acc2[2][4];
    #pragma unroll
    for (int p = 0; p < 2; p++)
        #pragma unroll
        for (int c = 0; c < 4; c++) acc2[p][c] = 0ull;

    const float4* Wp = (tx < 8) ? (W2m4 + tx) : (W2s4 + (tx - 8));
    #pragma unroll 8
    for (int i = 0; i < 64; i++) {
        float4 w4 = __ldg(Wp + i * 8);
        unsigned long long wd0, wd1, wd2, wd3;
        DUP_F32X2(wd0, w4.x); DUP_F32X2(wd1, w4.y);
        DUP_F32X2(wd2, w4.z); DUP_F32X2(wd3, w4.w);
        #pragma unroll
        for (int p = 0; p < 2; p++) {
            unsigned long long v2 =
                *(const unsigned long long*)&sHT[i * 66 + r0 + 2 * p];
            FFMA2(acc2[p][0], v2, wd0, acc2[p][0]);
            FFMA2(acc2[p][1], v2, wd1, acc2[p][1]);
            FFMA2(acc2[p][2], v2, wd2, acc2[p][2]);
            FFMA2(acc2[p][3], v2, wd3, acc2[p][3]);
        }
    }

    bool isP = (tx < 8);
    int txo = isP ? tx : tx - 8;
    #pragma unroll
    for (int p = 0; p < 2; p++) {
        float lo[4], hi[4];
        #pragma unroll
        for (int c = 0; c < 4; c++) UNPACK_F32X2(lo[c], hi[c], acc2[p][c]);
        int r = r0 + 2 * p;
        if (isP) {
            if (r < nn)
                g_p2h[(nb + r) * 8 + txo] =
                    make_uint2(f2h(lo[0], lo[1]), f2h(lo[2], lo[3]));
            if (r + 1 < nn)
                g_p2h[(nb + r + 1) * 8 + txo] =
                    make_uint2(f2h(hi[0], hi[1]), f2h(hi[2], hi[3]));
        } else {
            if (r < nn)
                g_s2[(nb + r) * 8 + txo] = make_float4(lo[0], lo[1], lo[2], lo[3]);
            if (r + 1 < nn)
                g_s2[(nb + r + 1) * 8 + txo] = make_float4(hi[0], hi[1], hi[2], hi[3]);
        }
    }
}

// ---------------- fused gather2 + node2 (R15-proven) --------------------------
__global__ __launch_bounds__(256) void k_gather2node2(
    const float4* __restrict__ W2m4,   // [80,32] -> f4 row stride 8
    const float* __restrict__ b2s, const float* __restrict__ b2m,
    float4* __restrict__ out4, int N)
{
    int t = blockIdx.x * 256 + threadIdx.x;
    int node = t >> 3;
    int j = t & 7;
    if (node >= N) return;
    int beg = g_rowptr[node];
    int cnt = g_rowptr[node + 1] - beg;
    const int2* csr = g_csr + beg;
    const uint2* p2 = (const uint2*)g_p2h;   // row stride 8 uint2

    float2 A0 = {0,0}, A1 = {0,0}, B0 = {0,0}, B1 = {0,0};
    float2 C0 = {0,0}, C1 = {0,0}, D0 = {0,0}, D1 = {0,0};
    int k = 0;
    for (; k + 4 <= cnt; k += 4) {
        int2 c0 = csr[k], c1 = csr[k + 1], c2 = csr[k + 2], c3 = csr[k + 3];
        uint2 u0 = __ldg(&p2[c0.x * 8 + j]);
        uint2 u1 = __ldg(&p2[c1.x * 8 + j]);
        uint2 u2 = __ldg(&p2[c2.x * 8 + j]);
        uint2 u3 = __ldg(&p2[c3.x * 8 + j]);
        float2 s;
        s = h2f(u0.x); A0.x += s.x; A0.y += s.y;
        s = h2f(u0.y); A1.x += s.x; A1.y += s.y;
        s = h2f(u1.x); B0.x += s.x; B0.y += s.y;
        s = h2f(u1.y); B1.x += s.x; B1.y += s.y;
        s = h2f(u2.x); C0.x += s.x; C0.y += s.y;
        s = h2f(u2.y); C1.x += s.x; C1.y += s.y;
        s = h2f(u3.x); D0.x += s.x; D0.y += s.y;
        s = h2f(u3.y); D1.x += s.x; D1.y += s.y;
    }
    for (; k < cnt; k++) {
        int2 c0 = csr[k];
        uint2 u0 = __ldg(&p2[c0.x * 8 + j]);
        float2 s;
        s = h2f(u0.x); A0.x += s.x; A0.y += s.y;
        s = h2f(u0.y); A1.x += s.x; A1.y += s.y;
    }
    float4 o = make_float4(A0.x + B0.x + C0.x + D0.x,
                           A0.y + B0.y + C0.y + D0.y,
                           A1.x + B1.x + C1.x + D1.x,
                           A1.y + B1.y + C1.y + D1.y);

    // epilogue: + S2 + b2s + deg*b2m + agge @ W2m_edge
    float deg = (float)cnt;
    float4 s2 = g_s2[node * 8 + j];
    float4 bS = __ldg(&((const float4*)b2s)[j]);
    float4 bM = __ldg(&((const float4*)b2m)[j]);
    o = make_float4(o.x + s2.x + bS.x + deg * bM.x,
                    o.y + s2.y + bS.y + deg * bM.y,
                    o.z + s2.z + bS.z + deg * bM.z,
                    o.w + s2.w + bS.w + deg * bM.w);
    float4 eg4[4];
    #pragma unroll
    for (int q = 0; q < 4; q++) eg4[q] = g_agge[node * 4 + q];
    float eg[16] = {eg4[0].x, eg4[0].y, eg4[0].z, eg4[0].w,
                    eg4[1].x, eg4[1].y, eg4[1].z, eg4[1].w,
                    eg4[2].x, eg4[2].y, eg4[2].z, eg4[2].w,
                    eg4[3].x, eg4[3].y, eg4[3].z, eg4[3].w};
    #pragma unroll
    for (int jj = 0; jj < 16; jj++)
        o = f4fma(eg[jj], __ldg(&W2m4[(64 + jj) * 8 + j]), o);

    out4[node * 8 + j] = o;
}

// ---------------- host --------------------------------------------------------
extern "C" void kernel_launch(void* const* d_in, const int* in_sizes, int n_in,
                              void* d_out, int out_size) {
    const float* x    = (const float*)d_in[0];
    const int*   ei   = (const int*)d_in[1];      // int32 (JAX x64 disabled)
    const float* ea   = (const float*)d_in[2];
    const float* W1m  = (const float*)d_in[3];
    const float* b1m  = (const float*)d_in[4];
    const float* W1s  = (const float*)d_in[5];
    const float* b1s  = (const float*)d_in[6];
    const float* gma  = (const float*)d_in[7];
    const float* bta  = (const float*)d_in[8];
    const float* mu   = (const float*)d_in[9];
    const float* var  = (const float*)d_in[10];
    const float* W2m  = (const float*)d_in[11];
    const float* b2m  = (const float*)d_in[12];
    const float* W2s  = (const float*)d_in[13];
    const float* b2s  = (const float*)d_in[14];

    int N = in_sizes[0] / 64;
    int E = in_sizes[1] / 2;
    const int* src = ei;
    const int* dst = ei + E;
    int nblk = (N + 1023) / 1024;
    int PB = (N + 63) / 64;

    // one-time host-side objects (no device work, no device allocation)
    static cudaStream_t s2 = nullptr;
    static cudaEvent_t evFork = nullptr, evJoin = nullptr;
    if (s2 == nullptr) {
        cudaStreamCreateWithFlags(&s2, cudaStreamNonBlocking);
        cudaEventCreateWithFlags(&evFork, cudaEventDisableTiming);
        cudaEventCreateWithFlags(&evJoin, cudaEventDisableTiming);
    }

    // fork: proj1 (independent) runs concurrently with the CSR chain
    cudaEventRecord(evFork, 0);
    cudaStreamWaitEvent(s2, evFork, 0);
    k_proj1<<<PB, 256, 0, s2>>>((const float4*)x, (const float4*)W1m,
                                (const float4*)W1s, N);
    cudaEventRecord(evJoin, s2);

    // CSR chain on the main stream
    k_hist<<<(E + 255) / 256, 256>>>(dst, E);
    k_scan<<<nblk, 1024>>>(N, E);
    k_scatter<<<(E + 255) / 256, 256>>>(src, dst, E);

    // join: gather1 needs proj1 + scatter
    cudaStreamWaitEvent(0, evJoin, 0);
    k_gather1<<<(N * 8 + 255) / 256, 256>>>((const float4*)ea, N);
    k_node1p2<<<PB, 256>>>(W1m, b1s, b1m, gma, bta, mu, var,
                           (const float4*)W2m, (const float4*)W2s, N);
    k_gather2node2<<<(N * 8 + 255) / 256, 256>>>((const float4*)W2m, b2s, b2m,
                                                 (float4*)d_out, N);
}